// round 16
// baseline (speedup 1.0000x reference)
#include <cuda_runtime.h>
#include <cuda_bf16.h>

// Problem dims
#define BATCH  64
#define SDIM   4096
#define DDIM   256
#define SCHUNK 512
#define NCHUNK (SDIM / SCHUNK)          // 8
#define NBLK   (BATCH * NCHUNK)         // 512 CTAs, occ 4, single wave
#define NPAIR  32                        // pairs of rows per warp (64 rows)

// Scratch for cross-CTA partials (no allocation allowed -> device globals)
__device__ float g_acc[NBLK * DDIM];    // 512 KB
__device__ float g_sum[NBLK];
__device__ int   g_cnt[BATCH];          // zero-init; re-armed by finalizer each run

__device__ __forceinline__ float warp_sum(float v) {
    #pragma unroll
    for (int o = 16; o; o >>= 1) v += __shfl_xor_sync(0xffffffffu, v, o);
    return v;
}

// exp(tanh(x)) via tanh(x) = 1 - 2/(e^{2x}+1); saturates correctly at +-1.
// Validated at rel_err ~1.0e-6 across R9-R14.
__device__ __forceinline__ float exp_tanh(float x) {
    const float t  = __expf(2.f * x);
    const float th = 1.f - __fdividef(2.f, t + 1.f);
    return __expf(th);
}

__device__ __forceinline__ float dot8(const float4& m0, const float4& m1,
                                      const float4& w0, const float4& w1) {
    return m0.x * w0.x + m0.y * w0.y + m0.z * w0.z + m0.w * w0.w
         + m1.x * w1.x + m1.y * w1.y + m1.z * w1.z + m1.w * w1.w;
}

__device__ __forceinline__ void cp_async16(void* smem, const void* gmem) {
    unsigned sa = (unsigned)__cvta_generic_to_shared(smem);
    asm volatile("cp.async.cg.shared.global [%0], [%1], 16;" :: "r"(sa), "l"(gmem));
}
__device__ __forceinline__ void cp_commit() {
    asm volatile("cp.async.commit_group;");
}
template<int N> __device__ __forceinline__ void cp_wait() {
    asm volatile("cp.async.wait_group %0;" :: "n"(N));
}

// ---------------------------------------------------------------------------
// Single pass over memory (268 MB read exactly once):
//   gi = tanh(m·Wm + c_b) in [-1,1] => exp never overflows => softmax needs
//   no running max; accumulate exp(gi)*m and exp(gi) in one sweep.
//
// Hybrid depth-6 pipeline per warp, ZERO hot-path syncs (R13 lesson):
//   - cp.async stages row-pairs k+1..k+3 into a lane-private 3-slot smem
//     ring (lane j writes & reads only its own 4 float4s -> wait_group is
//     the only ordering needed)
//   - LDS double-buffers the next pair into registers
//   - compute runs on the current pair (regs)
// 6 rows in flight/warp vs R14's 4, regs ~58 (no spill pressure).
// Last CTA per batch finalizes (threadfence-reduction pattern).
// ---------------------------------------------------------------------------
__global__ __launch_bounds__(256, 4)
void att_fused(const float* __restrict__ memory,
               const float* __restrict__ aspect,
               const float* __restrict__ W,
               const float* __restrict__ bias,
               float* __restrict__ out)
{
    // ring[warp][slot] = one row-pair: rows A (float4 0..63) and B (64..127)
    __shared__ __align__(16) float4 ring[8][3][128];   // 48 KB
    __shared__ float wsum[8];
    __shared__ int   s_old;

    const int tid  = threadIdx.x;
    const int lane = tid & 31;
    const int warp = tid >> 5;
    const int blk  = blockIdx.x;
    const int b    = blk >> 3;           // / NCHUNK
    const int chnk = blk & (NCHUNK - 1);

    const float4* base = reinterpret_cast<const float4*>(
        memory + ((long)b * SDIM + (long)chnk * SCHUNK) * DDIM);
    // this warp's rows r = warp + 8*j; pair k = rows (2k, 2k+1) of that set
    const float4* p = base + (long)warp * 64;
    const long rstep = 8 * 64;

    // stage pair k into ring slot s (lane-private: 4 x 16B per lane)
    auto stage = [&](int k, int s) {
        const float4* gA = p + (long)(2 * k)     * rstep;
        const float4* gB = p + (long)(2 * k + 1) * rstep;
        float4* sl = &ring[warp][s][0];
        cp_async16(&sl[lane],       gA + lane);
        cp_async16(&sl[32 + lane],  gA + 32 + lane);
        cp_async16(&sl[64 + lane],  gB + lane);
        cp_async16(&sl[96 + lane],  gB + 32 + lane);
        cp_commit();
    };

    // ---- FIRST: memory stream ignition (pair0 via LDG, pairs 1,2 async) ----
    float4 c00 = __ldcs(p + lane),         c01 = __ldcs(p + 32 + lane);
    float4 c10 = __ldcs(p + rstep + lane), c11 = __ldcs(p + rstep + 32 + lane);
    stage(1, 1);
    stage(2, 2);

    // ---- cb per-warp, sync-free (aspect/W are tiny, L2-broadcast) ----
    float cb;
    {
        float v = 0.f;
        #pragma unroll
        for (int k = 0; k < 8; k++)
            v += aspect[b * DDIM + lane + 32 * k] * W[DDIM + lane + 32 * k];
        cb = warp_sum(v) + bias[0];
    }

    // ---- Wm slice in registers: lane covers d = 4*lane.. and 128+4*lane.. ----
    const float4 wm0 = *reinterpret_cast<const float4*>(W + 4 * lane);
    const float4 wm1 = *reinterpret_cast<const float4*>(W + 128 + 4 * lane);

    float4 a0 = make_float4(0.f, 0.f, 0.f, 0.f);
    float4 a1 = make_float4(0.f, 0.f, 0.f, 0.f);
    float  sw = 0.f;

    #pragma unroll 3
    for (int k = 0; k < NPAIR; k++) {
        // issue pair k+3 into slot k%3 (freed by the LDS at iter k-1;
        // same-thread LDS precedes this LDGSTS, whose smem write lands
        // ~gmem-latency later — no hazard)
        if (k + 3 < NPAIR) stage(k + 3, k % 3);

        // wait so pair k+1 is resident; pending allowed = min(30-k, 2)
        float4 n00, n01, n10, n11;
        if (k < NPAIR - 1) {
            if      (k <= NPAIR - 4) cp_wait<2>();
            else if (k == NPAIR - 3) cp_wait<1>();
            else                     cp_wait<0>();
            const float4* sl = &ring[warp][(k + 1) % 3][0];
            n00 = sl[lane];       n01 = sl[32 + lane];
            n10 = sl[64 + lane];  n11 = sl[96 + lane];
        }

        // ---- compute pair k from registers ----
        float d0 = warp_sum(dot8(c00, c01, wm0, wm1));
        float d1 = warp_sum(dot8(c10, c11, wm0, wm1));
        const float w0 = exp_tanh(d0 + cb);
        const float w1 = exp_tanh(d1 + cb);

        a0.x += w0 * c00.x + w1 * c10.x;  a0.y += w0 * c00.y + w1 * c10.y;
        a0.z += w0 * c00.z + w1 * c10.z;  a0.w += w0 * c00.w + w1 * c10.w;
        a1.x += w0 * c01.x + w1 * c11.x;  a1.y += w0 * c01.y + w1 * c11.y;
        a1.z += w0 * c01.z + w1 * c11.z;  a1.w += w0 * c01.w + w1 * c11.w;
        sw   += w0 + w1;                  // uniform across lanes post-butterfly

        c00 = n00; c01 = n01; c10 = n10; c11 = n11;
    }

    // ---- deterministic 8-warp combine; slab overlays the dead ring ----
    __syncthreads();                      // all warps done with ring
    float* slab = reinterpret_cast<float*>(ring);      // [8][DDIM]
    float* my   = slab + warp * DDIM;
    my[4 * lane + 0] = a0.x;  my[4 * lane + 1] = a0.y;
    my[4 * lane + 2] = a0.z;  my[4 * lane + 3] = a0.w;
    my[128 + 4 * lane + 0] = a1.x;  my[128 + 4 * lane + 1] = a1.y;
    my[128 + 4 * lane + 2] = a1.z;  my[128 + 4 * lane + 3] = a1.w;
    if (lane == 0) wsum[warp] = sw;
    __syncthreads();

    {
        float t = 0.f;
        #pragma unroll
        for (int w = 0; w < 8; w++) t += slab[w * DDIM + tid];
        g_acc[blk * DDIM + tid] = t;
        if (tid == 0) {
            float s = 0.f;
            #pragma unroll
            for (int w = 0; w < 8; w++) s += wsum[w];
            g_sum[blk] = s;
        }
    }
    __syncthreads();

    // ---- last-CTA-per-batch finalize (threadfence-reduction pattern) ----
    if (tid == 0) {
        __threadfence();
        s_old = atomicAdd(&g_cnt[b], 1);
    }
    __syncthreads();
    if (s_old == NCHUNK - 1) {
        __threadfence();                  // acquire siblings' partials
        float acc = 0.f, s = 0.f;
        #pragma unroll
        for (int c = 0; c < NCHUNK; c++) {
            acc += g_acc[(b * NCHUNK + c) * DDIM + tid];
            s   += g_sum[b * NCHUNK + c];
        }
        out[b * DDIM + tid] = acc * __fdividef(1.f, s);
        __syncthreads();
        if (tid == 0) g_cnt[b] = 0;       // re-arm for next graph replay
    }
}

extern "C" void kernel_launch(void* const* d_in, const int* in_sizes, int n_in,
                              void* d_out, int out_size)
{
    // Map inputs by element count:
    //   memory: B*S*D = 67108864, aspect: B*D = 16384, W: 2*D = 512, b: 1
    const float *aspect = nullptr, *memory = nullptr, *W = nullptr, *bias = nullptr;
    for (int i = 0; i < n_in; i++) {
        const long n = (long)in_sizes[i];
        const float* p = (const float*)d_in[i];
        if      (n == (long)BATCH * SDIM * DDIM) memory = p;
        else if (n == (long)BATCH * DDIM)        aspect = p;
        else if (n == 2 * DDIM)                  W      = p;
        else if (n == 1)                         bias   = p;
    }

    att_fused<<<NBLK, 256>>>(memory, aspect, W, bias, (float*)d_out);
}

// round 17
// speedup vs baseline: 1.0831x; 1.0831x over previous
#include <cuda_runtime.h>
#include <cuda_bf16.h>

// Problem dims
#define BATCH  64
#define SDIM   4096
#define DDIM   256
#define SCHUNK 512
#define NCHUNK (SDIM / SCHUNK)          // 8
#define NBLK   (BATCH * NCHUNK)         // 512 CTAs, occ 4, single wave

// Scratch for cross-CTA partials (no allocation allowed -> device globals)
__device__ float g_acc[NBLK * DDIM];    // 512 KB
__device__ float g_sum[NBLK];
__device__ int   g_cnt[BATCH];          // zero-init; re-armed by finalizer each run

__device__ __forceinline__ float warp_sum(float v) {
    #pragma unroll
    for (int o = 16; o; o >>= 1) v += __shfl_xor_sync(0xffffffffu, v, o);
    return v;
}

// exp(tanh(x)) via tanh(x) = 1 - 2/(e^{2x}+1); saturates correctly at +-1.
// Validated at rel_err ~1.0e-6 across R9-R16.
__device__ __forceinline__ float exp_tanh(float x) {
    const float t  = __expf(2.f * x);
    const float th = 1.f - __fdividef(2.f, t + 1.f);
    return __expf(th);
}

__device__ __forceinline__ float dot8(const float4& m0, const float4& m1,
                                      const float4& w0, const float4& w1) {
    return m0.x * w0.x + m0.y * w0.y + m0.z * w0.z + m0.w * w0.w
         + m1.x * w1.x + m1.y * w1.y + m1.z * w1.z + m1.w * w1.w;
}

// ---------------------------------------------------------------------------
// Single pass over memory (268 MB read exactly once):
//   gi = tanh(m·Wm + c_b) in [-1,1] => exp never overflows => softmax needs
//   no running max; accumulate exp(gi)*m and exp(gi) in one sweep.
// Session-best structure (R14, 47.17us wall / 5.89 TB/s = ~98.5% of the
// achieved-BW floor for a one-pass read of 268 MB):
//   - first streaming loads issue BEFORE anything else (DRAM ramps at once)
//   - cb computed redundantly per-warp from L2-broadcast data: NO
//     __syncthreads anywhere before the hot loop (R13 lesson)
//   - register double-buffer, 2-row prefetch, guard-free steady state
//   - __ldcs evict-first: zero-reuse stream stays out of L2
// Measured invariants: 7 structural variants (cp.async CTA/lane-ring, TMA
// bulk, small CTAs, hybrid depth-6) all land at 5.4-5.9 TB/s -> this is the
// pattern's practical HBM ceiling; deeper pipelining does not pay.
// Last CTA per batch finalizes (threadfence-reduction pattern).
// ---------------------------------------------------------------------------
__global__ __launch_bounds__(256, 4)
void att_fused(const float* __restrict__ memory,
               const float* __restrict__ aspect,
               const float* __restrict__ W,
               const float* __restrict__ bias,
               float* __restrict__ out)
{
    __shared__ float slab[8][DDIM];      // per-warp partial vectors (8 KB)
    __shared__ float wsum[8];
    __shared__ int   s_old;

    const int tid  = threadIdx.x;
    const int lane = tid & 31;
    const int warp = tid >> 5;
    const int blk  = blockIdx.x;
    const int b    = blk >> 3;           // / NCHUNK
    const int chnk = blk & (NCHUNK - 1);

    const float4* base = reinterpret_cast<const float4*>(
        memory + ((long)b * SDIM + (long)chnk * SCHUNK) * DDIM);
    // row r occupies float4s [r*64, r*64+64); this warp does r = warp + 8*i
    const float4* p = base + (long)warp * 64;
    const long rstep = 8 * 64;           // 8 rows ahead per i

    // ---- FIRST: get the memory stream going (rows i=0,1 in flight) ----
    float4 c00 = __ldcs(p + lane),             c01 = __ldcs(p + 32 + lane);
    float4 c10 = __ldcs(p + rstep + lane),     c11 = __ldcs(p + rstep + 32 + lane);

    // ---- cb per-warp, sync-free (aspect/W are L2-broadcast, 1.3 KB) ----
    float cb;
    {
        float v = 0.f;
        #pragma unroll
        for (int k = 0; k < 8; k++)
            v += aspect[b * DDIM + lane + 32 * k] * W[DDIM + lane + 32 * k];
        cb = warp_sum(v) + bias[0];
    }

    // ---- Wm slice in registers: lane covers d = 4*lane.. and 128+4*lane.. ----
    const float4 wm0 = *reinterpret_cast<const float4*>(W + 4 * lane);
    const float4 wm1 = *reinterpret_cast<const float4*>(W + 128 + 4 * lane);

    float4 a0 = make_float4(0.f, 0.f, 0.f, 0.f);
    float4 a1 = make_float4(0.f, 0.f, 0.f, 0.f);
    float  sw = 0.f;

    // steady state: 31 iterations with unconditional 2-row prefetch
    #pragma unroll 2
    for (int i = 0; i < 62; i += 2) {
        const float4* q = p + (long)(i + 2) * rstep;
        const float4 n00 = __ldcs(q + lane);          const float4 n01 = __ldcs(q + 32 + lane);
        const float4 n10 = __ldcs(q + rstep + lane);  const float4 n11 = __ldcs(q + rstep + 32 + lane);

        float d0 = warp_sum(dot8(c00, c01, wm0, wm1));
        float d1 = warp_sum(dot8(c10, c11, wm0, wm1));
        const float w0 = exp_tanh(d0 + cb);
        const float w1 = exp_tanh(d1 + cb);

        a0.x += w0 * c00.x + w1 * c10.x;  a0.y += w0 * c00.y + w1 * c10.y;
        a0.z += w0 * c00.z + w1 * c10.z;  a0.w += w0 * c00.w + w1 * c10.w;
        a1.x += w0 * c01.x + w1 * c11.x;  a1.y += w0 * c01.y + w1 * c11.y;
        a1.z += w0 * c01.z + w1 * c11.z;  a1.w += w0 * c01.w + w1 * c11.w;
        sw   += w0 + w1;                  // uniform across lanes post-butterfly

        c00 = n00; c01 = n01; c10 = n10; c11 = n11;
    }
    // peeled final pair (rows 62,63 already resident in c**)
    {
        float d0 = warp_sum(dot8(c00, c01, wm0, wm1));
        float d1 = warp_sum(dot8(c10, c11, wm0, wm1));
        const float w0 = exp_tanh(d0 + cb);
        const float w1 = exp_tanh(d1 + cb);
        a0.x += w0 * c00.x + w1 * c10.x;  a0.y += w0 * c00.y + w1 * c10.y;
        a0.z += w0 * c00.z + w1 * c10.z;  a0.w += w0 * c00.w + w1 * c10.w;
        a1.x += w0 * c01.x + w1 * c11.x;  a1.y += w0 * c01.y + w1 * c11.y;
        a1.z += w0 * c01.z + w1 * c11.z;  a1.w += w0 * c01.w + w1 * c11.w;
        sw   += w0 + w1;
    }

    // ---- deterministic 8-warp combine via slab ----
    float* my = &slab[warp][0];
    my[4 * lane + 0] = a0.x;  my[4 * lane + 1] = a0.y;
    my[4 * lane + 2] = a0.z;  my[4 * lane + 3] = a0.w;
    my[128 + 4 * lane + 0] = a1.x;  my[128 + 4 * lane + 1] = a1.y;
    my[128 + 4 * lane + 2] = a1.z;  my[128 + 4 * lane + 3] = a1.w;
    if (lane == 0) wsum[warp] = sw;
    __syncthreads();

    {
        float t = 0.f;
        #pragma unroll
        for (int w = 0; w < 8; w++) t += slab[w][tid];
        g_acc[blk * DDIM + tid] = t;
        if (tid == 0) {
            float s = 0.f;
            #pragma unroll
            for (int w = 0; w < 8; w++) s += wsum[w];
            g_sum[blk] = s;
        }
    }
    __syncthreads();

    // ---- last-CTA-per-batch finalize (threadfence-reduction pattern) ----
    if (tid == 0) {
        __threadfence();
        s_old = atomicAdd(&g_cnt[b], 1);
    }
    __syncthreads();
    if (s_old == NCHUNK - 1) {
        __threadfence();                  // acquire siblings' partials
        float acc = 0.f, s = 0.f;
        #pragma unroll
        for (int c = 0; c < NCHUNK; c++) {
            acc += g_acc[(b * NCHUNK + c) * DDIM + tid];
            s   += g_sum[b * NCHUNK + c];
        }
        out[b * DDIM + tid] = acc * __fdividef(1.f, s);
        __syncthreads();
        if (tid == 0) g_cnt[b] = 0;       // re-arm for next graph replay
    }
}

extern "C" void kernel_launch(void* const* d_in, const int* in_sizes, int n_in,
                              void* d_out, int out_size)
{
    // Map inputs by element count:
    //   memory: B*S*D = 67108864, aspect: B*D = 16384, W: 2*D = 512, b: 1
    const float *aspect = nullptr, *memory = nullptr, *W = nullptr, *bias = nullptr;
    for (int i = 0; i < n_in; i++) {
        const long n = (long)in_sizes[i];
        const float* p = (const float*)d_in[i];
        if      (n == (long)BATCH * SDIM * DDIM) memory = p;
        else if (n == (long)BATCH * DDIM)        aspect = p;
        else if (n == 2 * DDIM)                  W      = p;
        else if (n == 1)                         bias   = p;
    }

    att_fused<<<NBLK, 256>>>(memory, aspect, W, bias, (float*)d_out);
}